// round 2
// baseline (speedup 1.0000x reference)
#include <cuda_runtime.h>
#include <math.h>

#define D_MODEL 1024
#define S_LEN   2048
#define BATCH   4
#define NHEAD   16
#define DKH     64
#define ROWS    (BATCH * S_LEN)   // 8192

// Scratch (static device globals — no runtime allocation)
__device__ float g_q[ROWS * D_MODEL];
__device__ float g_k[ROWS * D_MODEL];
__device__ float g_v[ROWS * D_MODEL];
__device__ float g_att[ROWS * D_MODEL];

// ---------------------------------------------------------------------------
// GEMM: Y = X @ W^T + bias.  X:[8192,1024], W:[1024,1024] row-major.
// 128x128 tile, BK=16, 256 threads, 8x8 micro-tile per thread.
// HEAD_MAJOR=true scatters output into [B, H, S, d_k] layout for attention.
// ---------------------------------------------------------------------------
template <bool HEAD_MAJOR>
__global__ __launch_bounds__(256)
void gemm_bias_kernel(const float* __restrict__ X, const float* __restrict__ W,
                      const float* __restrict__ bias, float* __restrict__ Y)
{
    constexpr int BM = 128, BN = 128, BK = 16;
    __shared__ float As[BK][BM];   // As[k][row]
    __shared__ float Bs[BK][BN];   // Bs[k][col]

    const int tid  = threadIdx.x;
    const int tx   = tid & 15;
    const int ty   = tid >> 4;
    const int row0 = blockIdx.x * BM;
    const int col0 = blockIdx.y * BN;

    const int lr = tid >> 2;         // 0..63
    const int lk = (tid & 3) << 2;   // 0,4,8,12

    float acc[8][8];
#pragma unroll
    for (int i = 0; i < 8; i++)
#pragma unroll
        for (int j = 0; j < 8; j++) acc[i][j] = 0.f;

    for (int k0 = 0; k0 < D_MODEL; k0 += BK) {
#pragma unroll
        for (int h = 0; h < 2; h++) {
            const int r = lr + h * 64;
            float4 va = *(const float4*)(X + (size_t)(row0 + r) * D_MODEL + k0 + lk);
            As[lk + 0][r] = va.x; As[lk + 1][r] = va.y;
            As[lk + 2][r] = va.z; As[lk + 3][r] = va.w;
            float4 vb = *(const float4*)(W + (size_t)(col0 + r) * D_MODEL + k0 + lk);
            Bs[lk + 0][r] = vb.x; Bs[lk + 1][r] = vb.y;
            Bs[lk + 2][r] = vb.z; Bs[lk + 3][r] = vb.w;
        }
        __syncthreads();

#pragma unroll
        for (int kk = 0; kk < BK; kk++) {
            float a[8], b[8];
            *(float4*)&a[0] = *(const float4*)&As[kk][ty * 8];
            *(float4*)&a[4] = *(const float4*)&As[kk][ty * 8 + 4];
            *(float4*)&b[0] = *(const float4*)&Bs[kk][tx * 8];
            *(float4*)&b[4] = *(const float4*)&Bs[kk][tx * 8 + 4];
#pragma unroll
            for (int i = 0; i < 8; i++)
#pragma unroll
                for (int j = 0; j < 8; j++) acc[i][j] += a[i] * b[j];
        }
        __syncthreads();
    }

    // Epilogue: add bias, write (optionally head-major)
#pragma unroll
    for (int i = 0; i < 8; i++) {
        const int r = row0 + ty * 8 + i;
#pragma unroll
        for (int j4 = 0; j4 < 8; j4 += 4) {
            const int c = col0 + tx * 8 + j4;
            float4 bv = *(const float4*)(bias + c);
            float4 v;
            v.x = acc[i][j4 + 0] + bv.x;
            v.y = acc[i][j4 + 1] + bv.y;
            v.z = acc[i][j4 + 2] + bv.z;
            v.w = acc[i][j4 + 3] + bv.w;
            if (HEAD_MAJOR) {
                const int b = r >> 11, s = r & 2047;
                const int h = c >> 6,  d = c & 63;
                *(float4*)(Y + ((size_t)((b * NHEAD + h) * S_LEN + s)) * DKH + d) = v;
            } else {
                *(float4*)(Y + (size_t)r * D_MODEL + c) = v;
            }
        }
    }
}

// ---------------------------------------------------------------------------
// Flash attention (fp32). Block = (q-tile of 64 rows) x (one b,h). 256 threads.
// Both QK^T and PV are 4x4 micro-tiled smem GEMMs. Softmax state in registers;
// row reductions via shfl within half-warps (lane bits 0..3 == tx).
// Ps (probabilities) aliases Kt smem.
// ---------------------------------------------------------------------------
__global__ __launch_bounds__(256)
void attn_kernel(const float* __restrict__ Q, const float* __restrict__ K,
                 const float* __restrict__ V, float* __restrict__ O)
{
    __shared__ float Qt[64][64];   // Qt[d][r]
    __shared__ float Kt[64][64];   // Kt[d][c] during scores; Ps[r][k] during PV
    __shared__ float Vs[64][64];   // Vs[k][d]
    float (*Ps)[64] = Kt;

    const int tid = threadIdx.x;
    const int tx  = tid & 15;
    const int ty  = tid >> 4;
    const int bh  = blockIdx.y;
    const int q0  = blockIdx.x * 64;

    const float* qb = Q + ((size_t)bh * S_LEN + q0) * DKH;
    const float* kb = K + (size_t)bh * S_LEN * DKH;
    const float* vb = V + (size_t)bh * S_LEN * DKH;

    const int lr = tid >> 2;          // 0..63
    const int lc = (tid & 3) << 4;    // 0,16,32,48

    // Load Q tile transposed: Qt[d][r]
#pragma unroll
    for (int u = 0; u < 4; u++) {
        float4 v = *(const float4*)(qb + (size_t)lr * DKH + lc + u * 4);
        Qt[lc + u * 4 + 0][lr] = v.x; Qt[lc + u * 4 + 1][lr] = v.y;
        Qt[lc + u * 4 + 2][lr] = v.z; Qt[lc + u * 4 + 3][lr] = v.w;
    }

    float o[4][4];
    float m[4], l[4];
#pragma unroll
    for (int i = 0; i < 4; i++) {
        m[i] = -1e30f; l[i] = 0.f;
#pragma unroll
        for (int j = 0; j < 4; j++) o[i][j] = 0.f;
    }
    const float scale = 0.125f;  // 1/sqrt(64)

    for (int kt = 0; kt < S_LEN; kt += 64) {
        __syncthreads();  // prev-iter Ps/Vs reads (and initial Qt stores) done

        // Load K tile transposed (Kt[d][c]) and V tile row-major (Vs[k][d])
#pragma unroll
        for (int u = 0; u < 4; u++) {
            float4 v = *(const float4*)(kb + (size_t)(kt + lr) * DKH + lc + u * 4);
            Kt[lc + u * 4 + 0][lr] = v.x; Kt[lc + u * 4 + 1][lr] = v.y;
            Kt[lc + u * 4 + 2][lr] = v.z; Kt[lc + u * 4 + 3][lr] = v.w;
            float4 w = *(const float4*)(vb + (size_t)(kt + lr) * DKH + lc + u * 4);
            *(float4*)&Vs[lr][lc + u * 4] = w;
        }
        __syncthreads();

        // Scores: s[i][j] = Q[r_i,:] . K[c_j,:]
        float s[4][4];
#pragma unroll
        for (int i = 0; i < 4; i++)
#pragma unroll
            for (int j = 0; j < 4; j++) s[i][j] = 0.f;

#pragma unroll 8
        for (int d = 0; d < DKH; d++) {
            float a[4], b[4];
            *(float4*)a = *(const float4*)&Qt[d][ty * 4];
            *(float4*)b = *(const float4*)&Kt[d][tx * 4];
#pragma unroll
            for (int i = 0; i < 4; i++)
#pragma unroll
                for (int j = 0; j < 4; j++) s[i][j] += a[i] * b[j];
        }
        __syncthreads();  // all Kt reads done before Ps (aliased) writes

        // Online softmax per row (rows ty*4+i, shared across the 16 tx lanes)
#pragma unroll
        for (int i = 0; i < 4; i++) {
            float tmax = -1e30f;
#pragma unroll
            for (int j = 0; j < 4; j++) {
                s[i][j] *= scale;
                tmax = fmaxf(tmax, s[i][j]);
            }
            tmax = fmaxf(tmax, __shfl_xor_sync(0xffffffffu, tmax, 1));
            tmax = fmaxf(tmax, __shfl_xor_sync(0xffffffffu, tmax, 2));
            tmax = fmaxf(tmax, __shfl_xor_sync(0xffffffffu, tmax, 4));
            tmax = fmaxf(tmax, __shfl_xor_sync(0xffffffffu, tmax, 8));
            const float mn   = fmaxf(m[i], tmax);
            const float corr = __expf(m[i] - mn);
            m[i] = mn;
            float p[4], ls = 0.f;
#pragma unroll
            for (int j = 0; j < 4; j++) { p[j] = __expf(s[i][j] - mn); ls += p[j]; }
            ls += __shfl_xor_sync(0xffffffffu, ls, 1);
            ls += __shfl_xor_sync(0xffffffffu, ls, 2);
            ls += __shfl_xor_sync(0xffffffffu, ls, 4);
            ls += __shfl_xor_sync(0xffffffffu, ls, 8);
            l[i] = l[i] * corr + ls;
#pragma unroll
            for (int j = 0; j < 4; j++) o[i][j] *= corr;
            *(float4*)&Ps[ty * 4 + i][tx * 4] = make_float4(p[0], p[1], p[2], p[3]);
        }
        __syncthreads();

        // PV: o[i][j] += sum_k Ps[r_i][k] * Vs[k][c_j]
#pragma unroll 4
        for (int k0 = 0; k0 < 64; k0 += 4) {
            float av[4][4];
#pragma unroll
            for (int i = 0; i < 4; i++) {
                float4 t = *(const float4*)&Ps[ty * 4 + i][k0];
                av[i][0] = t.x; av[i][1] = t.y; av[i][2] = t.z; av[i][3] = t.w;
            }
#pragma unroll
            for (int kk = 0; kk < 4; kk++) {
                float b[4];
                *(float4*)b = *(const float4*)&Vs[k0 + kk][tx * 4];
#pragma unroll
                for (int i = 0; i < 4; i++)
#pragma unroll
                    for (int j = 0; j < 4; j++) o[i][j] += av[i][kk] * b[j];
            }
        }
    }

    // Normalize and write to g_att in [B, S, D] layout
    const int bb = bh >> 4, h = bh & 15;
#pragma unroll
    for (int i = 0; i < 4; i++) {
        const float inv = 1.f / l[i];
        const size_t row = (size_t)bb * S_LEN + q0 + ty * 4 + i;
        float4 v = make_float4(o[i][0] * inv, o[i][1] * inv,
                               o[i][2] * inv, o[i][3] * inv);
        *(float4*)(O + row * D_MODEL + h * DKH + tx * 4) = v;
    }
}

// ---------------------------------------------------------------------------
extern "C" void kernel_launch(void* const* d_in, const int* in_sizes, int n_in,
                              void* d_out, int out_size)
{
    (void)in_sizes; (void)n_in; (void)out_size;
    const float* x  = (const float*)d_in[0];
    const float* wq = (const float*)d_in[1];
    const float* bq = (const float*)d_in[2];
    const float* wk = (const float*)d_in[3];
    const float* bk = (const float*)d_in[4];
    const float* wv = (const float*)d_in[5];
    const float* bv = (const float*)d_in[6];
    const float* wo = (const float*)d_in[7];
    const float* bo = (const float*)d_in[8];
    float* out = (float*)d_out;

    float *q, *k, *v, *att;
    cudaGetSymbolAddress((void**)&q,   g_q);
    cudaGetSymbolAddress((void**)&k,   g_k);
    cudaGetSymbolAddress((void**)&v,   g_v);
    cudaGetSymbolAddress((void**)&att, g_att);

    dim3 ggrid(ROWS / 128, D_MODEL / 128);
    gemm_bias_kernel<true><<<ggrid, 256>>>(x, wq, bq, q);
    gemm_bias_kernel<true><<<ggrid, 256>>>(x, wk, bk, k);
    gemm_bias_kernel<true><<<ggrid, 256>>>(x, wv, bv, v);

    dim3 agrid(S_LEN / 64, BATCH * NHEAD);
    attn_kernel<<<agrid, 256>>>(q, k, v, att);

    gemm_bias_kernel<false><<<ggrid, 256>>>(att, wo, bo, out);
}